// round 1
// baseline (speedup 1.0000x reference)
#include <cuda_runtime.h>

// Problem constants
#define NQ        20
#define S_LOG     20
#define BATCH     16
// elements per warp = 32 regs * 32 lanes = 1024
// total warps = BATCH * 2^20 / 1024 = 16384
#define TOTAL_WARPS   16384
#define WARPS_PER_BLK 8
#define BLK_THREADS   (WARPS_PER_BLK * 32)
#define GRID_BLKS     (TOTAL_WARPS / WARPS_PER_BLK)

// RX butterfly on pair (a,b) with c=cos(th/2), s=sin(th/2):
//   na = c*a + (-i s)*b  ->  na.x = c*ax + s*by ; na.y = c*ay - s*bx
//   nb = (-i s)*a + c*b  ->  nb.x = c*bx + s*ay ; nb.y = c*by - s*ax
// Symmetric in (a,b): each element's update is
//   new.x = c*self.x + s*partner.y ; new.y = c*self.y - s*partner.x

__device__ __forceinline__ void reg_stages(float2 v[32], const float* __restrict__ thetas,
                                           int b, int bit_base)
{
#pragma unroll
    for (int p = 0; p < 5; ++p) {
        float th = thetas[b * NQ + (NQ - 1 - (bit_base + p))];
        float s, c;
        __sincosf(0.5f * th, &s, &c);
        const int m = 1 << p;
#pragma unroll
        for (int r = 0; r < 32; ++r) {
            if (!(r & m)) {
                const int r2 = r | m;
                float ax = v[r].x,  ay = v[r].y;
                float bx = v[r2].x, by = v[r2].y;
                v[r].x  = c * ax + s * by;
                v[r].y  = c * ay - s * bx;
                v[r2].x = c * bx + s * ay;
                v[r2].y = c * by - s * ax;
            }
        }
    }
}

// ---------------------------------------------------------------------------
// Pass A: qubit bits 0..9. Warp owns 1024 contiguous amplitudes.
//   bits 0..4  -> register index r (register butterflies)
//   bits 5..9  -> lane index      (shuffle butterflies)
// Reads real phi, writes complex (float2) out.
// ---------------------------------------------------------------------------
__global__ void __launch_bounds__(BLK_THREADS)
rx_pass_a(const float* __restrict__ phi,
          const float* __restrict__ thetas,
          float2* __restrict__ out)
{
    const int g    = blockIdx.x * WARPS_PER_BLK + (threadIdx.x >> 5);
    const int lane = threadIdx.x & 31;
    const int b    = g >> 10;                      // 1024 chunks per batch
    const long base = ((long)g << 10) + lane * 32; // global element index

    float2 v[32];
    const float4* p4 = reinterpret_cast<const float4*>(phi + base);
#pragma unroll
    for (int k = 0; k < 8; ++k) {
        float4 t = p4[k];
        v[4*k+0] = make_float2(t.x, 0.0f);
        v[4*k+1] = make_float2(t.y, 0.0f);
        v[4*k+2] = make_float2(t.z, 0.0f);
        v[4*k+3] = make_float2(t.w, 0.0f);
    }

    // bits 0..4 in registers
    reg_stages(v, thetas, b, 0);

    // bits 5..9 across lanes (branch-free symmetric butterfly)
#pragma unroll
    for (int q = 0; q < 5; ++q) {
        float th = thetas[b * NQ + (NQ - 1 - (5 + q))];
        float s, c;
        __sincosf(0.5f * th, &s, &c);
#pragma unroll
        for (int r = 0; r < 32; ++r) {
            float px = __shfl_xor_sync(0xffffffffu, v[r].x, 1 << q);
            float py = __shfl_xor_sync(0xffffffffu, v[r].y, 1 << q);
            float nx = c * v[r].x + s * py;
            float ny = c * v[r].y - s * px;
            v[r].x = nx;
            v[r].y = ny;
        }
    }

    float4* o4 = reinterpret_cast<float4*>(out + base);
#pragma unroll
    for (int k = 0; k < 16; ++k)
        o4[k] = make_float4(v[2*k].x, v[2*k].y, v[2*k+1].x, v[2*k+1].y);
}

// ---------------------------------------------------------------------------
// Pass B: qubit bits SHIFT..SHIFT+4 (SHIFT = 10 or 15), in-place on out.
//   bits 0..4          -> lane (coalesced 256B accesses)
//   bits SHIFT..SHIFT+4 -> register index (pure register butterflies)
// Every warp touches a disjoint 1024-element set -> safe in place.
// ---------------------------------------------------------------------------
template<int SHIFT>
__global__ void __launch_bounds__(BLK_THREADS)
rx_pass_b(const float* __restrict__ thetas, float2* __restrict__ st)
{
    const int g    = blockIdx.x * WARPS_PER_BLK + (threadIdx.x >> 5);
    const int lane = threadIdx.x & 31;
    const int b    = g >> 10;
    const int rem  = g & 1023;

    long base;
    if (SHIFT == 10) {
        // fixed bits: 5..9 (m) and 15..19 (u)
        const int u = rem >> 5;
        const int m = rem & 31;
        base = ((long)b << S_LOG) + ((long)u << 15) + ((long)m << 5) + lane;
    } else {
        // SHIFT == 15: fixed bits 5..14 (rem)
        base = ((long)b << S_LOG) + ((long)rem << 5) + lane;
    }

    float2 v[32];
#pragma unroll
    for (int r = 0; r < 32; ++r)
        v[r] = st[base + ((long)r << SHIFT)];

    reg_stages(v, thetas, b, SHIFT);

#pragma unroll
    for (int r = 0; r < 32; ++r)
        st[base + ((long)r << SHIFT)] = v[r];
}

// ---------------------------------------------------------------------------
extern "C" void kernel_launch(void* const* d_in, const int* in_sizes, int n_in,
                              void* d_out, int out_size)
{
    const float* phi    = (const float*)d_in[0];   // [16, 2^20] float32
    const float* thetas = (const float*)d_in[1];   // [16, 20]   float32
    float2* out = (float2*)d_out;                  // [16, 2^20] (re, im)

    rx_pass_a<<<GRID_BLKS, BLK_THREADS>>>(phi, thetas, out);
    rx_pass_b<10><<<GRID_BLKS, BLK_THREADS>>>(thetas, out);
    rx_pass_b<15><<<GRID_BLKS, BLK_THREADS>>>(thetas, out);
}

// round 2
// speedup vs baseline: 1.7079x; 1.7079x over previous
#include <cuda_runtime.h>

#define NQ 20
typedef unsigned long long u64;

// ---------------- f32x2 helpers (packed 2xfp32 ops, sm_103a) ----------------
__device__ __forceinline__ u64 pk(float lo, float hi) {
    u64 r; asm("mov.b64 %0,{%1,%2};" : "=l"(r) : "f"(lo), "f"(hi)); return r;
}
__device__ __forceinline__ void upk(u64 p, float& lo, float& hi) {
    asm("mov.b64 {%0,%1},%2;" : "=f"(lo), "=f"(hi) : "l"(p));
}
__device__ __forceinline__ u64 f2mul(u64 a, u64 b) {
    u64 r; asm("mul.rn.f32x2 %0,%1,%2;" : "=l"(r) : "l"(a), "l"(b)); return r;
}
__device__ __forceinline__ u64 f2fma(u64 a, u64 b, u64 c) {
    u64 r; asm("fma.rn.f32x2 %0,%1,%2,%3;" : "=l"(r) : "l"(a), "l"(b), "l"(c)); return r;
}

// RX butterfly on pair (a,b), c=cos(th/2), s=sin(th/2):
//   na.x = c*ax + s*by ; na.y = c*ay - s*bx
//   nb.x = c*bx + s*ay ; nb.y = c*by - s*ax
// State: 32 complex elements as PX[16], PY[16]; pack q holds elements (2q, 2q+1).
__device__ __forceinline__ void stages5(u64 PX[16], u64 PY[16], const float2 cs[5])
{
    // stage 0: element mask 1 (intra-pack, packed swap trick)
    {
        u64 c2  = pk(cs[0].x,  cs[0].x);
        u64 s2  = pk(cs[0].y,  cs[0].y);
        u64 sn2 = pk(-cs[0].y, -cs[0].y);
#pragma unroll
        for (int q = 0; q < 16; ++q) {
            float xl, xh, yl, yh;
            upk(PX[q], xl, xh); upk(PY[q], yl, yh);
            u64 swx = pk(xh, xl), swy = pk(yh, yl);
            PX[q] = f2fma(c2, PX[q], f2mul(s2,  swy));
            PY[q] = f2fma(c2, PY[q], f2mul(sn2, swx));
        }
    }
    // stages 1..4: element mask 2^j -> pack mask 2^(j-1), pure f32x2
#pragma unroll
    for (int j = 1; j < 5; ++j) {
        u64 c2  = pk(cs[j].x,  cs[j].x);
        u64 s2  = pk(cs[j].y,  cs[j].y);
        u64 sn2 = pk(-cs[j].y, -cs[j].y);
        const int pm = 1 << (j - 1);
#pragma unroll
        for (int q = 0; q < 16; ++q) {
            if (!(q & pm)) {
                const int q2 = q | pm;
                u64 ax = PX[q], ay = PY[q], bx = PX[q2], by = PY[q2];
                PX[q]  = f2fma(c2, ax, f2mul(s2,  by));
                PY[q]  = f2fma(c2, ay, f2mul(sn2, bx));
                PX[q2] = f2fma(c2, bx, f2mul(s2,  ay));
                PY[q2] = f2fma(c2, by, f2mul(sn2, ax));
            }
        }
    }
}

// qubit i = most-significant bit => global bit g maps to theta index (19-g)
__device__ __forceinline__ void load_cs(const float* __restrict__ thetas, int b,
                                        int gbit_base, float2 cs[5])
{
#pragma unroll
    for (int j = 0; j < 5; ++j) {
        float th = thetas[b * NQ + (NQ - 1 - (gbit_base + j))];
        float s, c;
        __sincosf(0.5f * th, &s, &c);
        cs[j] = make_float2(c, s);
    }
}

// ---------------------------------------------------------------------------
// Pass A: global bits 0..9. Each warp owns 1024 contiguous elements.
//   phase 1: regs = bits 0..4 (stages), lanes = bits 5..9
//   warp-private padded smem transpose (X then Y, reusing one buffer)
//   phase 2: regs = bits 5..9 (stages), lanes = bits 0..4
// Reads real phi, writes complex out. Fully coalesced both ends.
// ---------------------------------------------------------------------------
__global__ void __launch_bounds__(256)
rx_a(const float* __restrict__ phi, const float* __restrict__ thetas,
     float2* __restrict__ out)
{
    __shared__ float sm[8][34 * 32];   // per-warp 32x32 tile, row pad 34
    const int w    = threadIdx.x >> 5;
    const int lane = threadIdx.x & 31;
    const long gw  = (long)blockIdx.x * 8 + w;   // 16384 warps total
    const int  b   = (int)(gw >> 10);            // batch
    const long base = gw << 10;                  // element base (within phi/out)

    float2 cs1[5], cs2[5];
    load_cs(thetas, b, 0, cs1);
    load_cs(thetas, b, 5, cs2);

    // load 32 consecutive floats (real), imag = 0
    u64 PX[16], PY[16];
    const float4* p4 = reinterpret_cast<const float4*>(phi + base + lane * 32);
#pragma unroll
    for (int k = 0; k < 8; ++k) {
        float4 t = p4[k];
        PX[2 * k]     = pk(t.x, t.y);
        PX[2 * k + 1] = pk(t.z, t.w);
        PY[2 * k]     = 0ull;
        PY[2 * k + 1] = 0ull;
    }

    stages5(PX, PY, cs1);          // bits 0..4

    float* X = sm[w];
    // transpose X: element e stored at (e&31)*34 + (e>>5); phase1 e = lane*32 + r
#pragma unroll
    for (int q = 0; q < 16; ++q) {
        float l, h; upk(PX[q], l, h);
        X[(2 * q) * 34 + lane]     = l;
        X[(2 * q + 1) * 34 + lane] = h;
    }
    __syncwarp();
#pragma unroll
    for (int q = 0; q < 16; ++q) {   // phase2 e = r'*32 + lane -> idx = lane*34 + r'
        float2 t = *reinterpret_cast<float2*>(&X[lane * 34 + 2 * q]);
        PX[q] = pk(t.x, t.y);
    }
    __syncwarp();
    // transpose Y (reuse buffer)
#pragma unroll
    for (int q = 0; q < 16; ++q) {
        float l, h; upk(PY[q], l, h);
        X[(2 * q) * 34 + lane]     = l;
        X[(2 * q + 1) * 34 + lane] = h;
    }
    __syncwarp();
#pragma unroll
    for (int q = 0; q < 16; ++q) {
        float2 t = *reinterpret_cast<float2*>(&X[lane * 34 + 2 * q]);
        PY[q] = pk(t.x, t.y);
    }

    stages5(PX, PY, cs2);          // bits 5..9

    // store: element e = r'*32 + lane -> per instruction 32 consecutive float2
#pragma unroll
    for (int q = 0; q < 16; ++q) {
        float xl, xh, yl, yh;
        upk(PX[q], xl, xh); upk(PY[q], yl, yh);
        out[base + (2 * q) * 32 + lane]     = make_float2(xl, yl);
        out[base + (2 * q + 1) * 32 + lane] = make_float2(xh, yh);
    }
}

// ---------------------------------------------------------------------------
// Pass B: global bits 10..19, in place on out. Block tile = 8 low x 1024 high.
//   threads: low = t&7 (8 consecutive low addresses -> 64B segments),
//            g5  = t>>3 (bits 15..19)
//   phase 1: regs = bits 10..14 (stages)
//   block-wide padded smem transpose (X then Y)
//   phase 2: regs = bits 15..19 (stages), fixed = bits 10..14
// ---------------------------------------------------------------------------
__global__ void __launch_bounds__(256)
rx_b(const float* __restrict__ thetas, float2* __restrict__ st)
{
    __shared__ float sm[32 * 264];   // [i5][j5][low], row pad 264 (8 mod 16 banks trick)
    const int t   = threadIdx.x;
    const int low = t & 7;
    const int g5  = t >> 3;          // 0..31
    const int blk   = blockIdx.x;    // 2048 blocks
    const int b     = blk >> 7;      // batch
    const int chunk = blk & 127;     // which 8-wide low chunk (bits 3..9)
    const long base = ((long)b << 20) + ((long)chunk << 3) + low;

    float2 cs1[5], cs2[5];
    load_cs(thetas, b, 10, cs1);
    load_cs(thetas, b, 15, cs2);

    u64 PX[16], PY[16];
    const long a0 = base + ((long)g5 << 15);
#pragma unroll
    for (int q = 0; q < 16; ++q) {
        float2 v0 = st[a0 + ((long)(2 * q) << 10)];
        float2 v1 = st[a0 + ((long)(2 * q + 1) << 10)];
        PX[q] = pk(v0.x, v1.x);
        PY[q] = pk(v0.y, v1.y);
    }

    stages5(PX, PY, cs1);           // bits 10..14

    // transpose X: logical [i5][j5][low] -> sm[i5*264 + j5*8 + low]
    // phase1: i5 = g5 (bits 15..19), j5 = r (bits 10..14)
#pragma unroll
    for (int q = 0; q < 16; ++q) {
        float l, h; upk(PX[q], l, h);
        sm[g5 * 264 + (2 * q) * 8 + low]     = l;
        sm[g5 * 264 + (2 * q + 1) * 8 + low] = h;
    }
    __syncthreads();
#pragma unroll
    for (int q = 0; q < 16; ++q) {   // phase2: i5 = r' (bits 15..19), j5 = f5 = t>>3
        float l = sm[(2 * q) * 264 + g5 * 8 + low];
        float h = sm[(2 * q + 1) * 264 + g5 * 8 + low];
        PX[q] = pk(l, h);
    }
    __syncthreads();
    // transpose Y
#pragma unroll
    for (int q = 0; q < 16; ++q) {
        float l, h; upk(PY[q], l, h);
        sm[g5 * 264 + (2 * q) * 8 + low]     = l;
        sm[g5 * 264 + (2 * q + 1) * 8 + low] = h;
    }
    __syncthreads();
#pragma unroll
    for (int q = 0; q < 16; ++q) {
        float l = sm[(2 * q) * 264 + g5 * 8 + low];
        float h = sm[(2 * q + 1) * 264 + g5 * 8 + low];
        PY[q] = pk(l, h);
    }

    stages5(PX, PY, cs2);           // bits 15..19

    // store: element = base + f5<<10 + r'<<15, f5 = g5 (t>>3)
    const long a1 = base + ((long)g5 << 10);
#pragma unroll
    for (int q = 0; q < 16; ++q) {
        float xl, xh, yl, yh;
        upk(PX[q], xl, xh); upk(PY[q], yl, yh);
        st[a1 + ((long)(2 * q) << 15)]     = make_float2(xl, yl);
        st[a1 + ((long)(2 * q + 1) << 15)] = make_float2(xh, yh);
    }
}

// ---------------------------------------------------------------------------
extern "C" void kernel_launch(void* const* d_in, const int* in_sizes, int n_in,
                              void* d_out, int out_size)
{
    const float* phi    = (const float*)d_in[0];   // [16, 2^20] float32
    const float* thetas = (const float*)d_in[1];   // [16, 20]   float32
    float2* out = (float2*)d_out;                  // [16, 2^20] (re, im)

    rx_a<<<2048, 256>>>(phi, thetas, out);
    rx_b<<<2048, 256>>>(thetas, out);
}

// round 3
// speedup vs baseline: 1.9378x; 1.1346x over previous
#include <cuda_runtime.h>

#define NQ 20
typedef unsigned long long u64;

// ---------------- f32x2 helpers (packed 2xfp32 ops, sm_103a) ----------------
__device__ __forceinline__ u64 pk(float lo, float hi) {
    u64 r; asm("mov.b64 %0,{%1,%2};" : "=l"(r) : "f"(lo), "f"(hi)); return r;
}
__device__ __forceinline__ void upk(u64 p, float& lo, float& hi) {
    asm("mov.b64 {%0,%1},%2;" : "=f"(lo), "=f"(hi) : "l"(p));
}
__device__ __forceinline__ u64 f2mul(u64 a, u64 b) {
    u64 r; asm("mul.rn.f32x2 %0,%1,%2;" : "=l"(r) : "l"(a), "l"(b)); return r;
}
__device__ __forceinline__ u64 f2fma(u64 a, u64 b, u64 c) {
    u64 r; asm("fma.rn.f32x2 %0,%1,%2,%3;" : "=l"(r) : "l"(a), "l"(b), "l"(c)); return r;
}

// RX butterfly on pair (a,b), c=cos(th/2), s=sin(th/2):
//   na.x = c*ax + s*by ; na.y = c*ay - s*bx
//   nb.x = c*bx + s*ay ; nb.y = c*by - s*ax
__device__ __forceinline__ void stages5(u64 PX[16], u64 PY[16], const float2 cs[5])
{
    // stage 0: element mask 1 (intra-pack, packed swap)
    {
        u64 c2  = pk(cs[0].x,  cs[0].x);
        u64 s2  = pk(cs[0].y,  cs[0].y);
        u64 sn2 = pk(-cs[0].y, -cs[0].y);
#pragma unroll
        for (int q = 0; q < 16; ++q) {
            float xl, xh, yl, yh;
            upk(PX[q], xl, xh); upk(PY[q], yl, yh);
            u64 swx = pk(xh, xl), swy = pk(yh, yl);
            PX[q] = f2fma(c2, PX[q], f2mul(s2,  swy));
            PY[q] = f2fma(c2, PY[q], f2mul(sn2, swx));
        }
    }
    // stages 1..4: element mask 2^j -> pack mask 2^(j-1)
#pragma unroll
    for (int j = 1; j < 5; ++j) {
        u64 c2  = pk(cs[j].x,  cs[j].x);
        u64 s2  = pk(cs[j].y,  cs[j].y);
        u64 sn2 = pk(-cs[j].y, -cs[j].y);
        const int pm = 1 << (j - 1);
#pragma unroll
        for (int q = 0; q < 16; ++q) {
            if (!(q & pm)) {
                const int q2 = q | pm;
                u64 ax = PX[q], ay = PY[q], bx = PX[q2], by = PY[q2];
                PX[q]  = f2fma(c2, ax, f2mul(s2,  by));
                PY[q]  = f2fma(c2, ay, f2mul(sn2, bx));
                PX[q2] = f2fma(c2, bx, f2mul(s2,  ay));
                PY[q2] = f2fma(c2, by, f2mul(sn2, ax));
            }
        }
    }
}

// qubit i = most-significant bit => global bit g maps to theta index (19-g)
__device__ __forceinline__ void load_cs(const float* __restrict__ thetas, int b,
                                        int gbit_base, float2 cs[5])
{
#pragma unroll
    for (int j = 0; j < 5; ++j) {
        float th = thetas[b * NQ + (NQ - 1 - (gbit_base + j))];
        float s, c;
        __sincosf(0.5f * th, &s, &c);
        cs[j] = make_float2(c, s);
    }
}

// ---------------------------------------------------------------------------
// Pass A: global bits 0..9 for an 8-batch group. Warp owns 1024 contiguous
// elements. phi read streaming (__ldcs); intermediate writes default policy
// (keep L2-resident for pass B).
// ---------------------------------------------------------------------------
__global__ void __launch_bounds__(256)
rx_a(const float* __restrict__ phi, const float* __restrict__ thetas,
     float2* __restrict__ out, int batch_base)
{
    __shared__ float sm[8][34 * 32];
    const int w    = threadIdx.x >> 5;
    const int lane = threadIdx.x & 31;
    const long gw  = (long)blockIdx.x * 8 + w;        // 8192 warps per group
    const int  b   = batch_base + (int)(gw >> 10);
    const long base = ((long)b << 20) + (long)(gw & 1023) * 1024;

    float2 cs1[5], cs2[5];
    load_cs(thetas, b, 0, cs1);
    load_cs(thetas, b, 5, cs2);

    u64 PX[16], PY[16];
    const float4* p4 = reinterpret_cast<const float4*>(phi + base + lane * 32);
#pragma unroll
    for (int k = 0; k < 8; ++k) {
        float4 t = __ldcs(p4 + k);          // streaming read-once
        PX[2 * k]     = pk(t.x, t.y);
        PX[2 * k + 1] = pk(t.z, t.w);
        PY[2 * k]     = 0ull;
        PY[2 * k + 1] = 0ull;
    }

    stages5(PX, PY, cs1);          // bits 0..4

    float* X = sm[w];
#pragma unroll
    for (int q = 0; q < 16; ++q) {
        float l, h; upk(PX[q], l, h);
        X[(2 * q) * 34 + lane]     = l;
        X[(2 * q + 1) * 34 + lane] = h;
    }
    __syncwarp();
#pragma unroll
    for (int q = 0; q < 16; ++q) {
        float2 t = *reinterpret_cast<float2*>(&X[lane * 34 + 2 * q]);
        PX[q] = pk(t.x, t.y);
    }
    __syncwarp();
#pragma unroll
    for (int q = 0; q < 16; ++q) {
        float l, h; upk(PY[q], l, h);
        X[(2 * q) * 34 + lane]     = l;
        X[(2 * q + 1) * 34 + lane] = h;
    }
    __syncwarp();
#pragma unroll
    for (int q = 0; q < 16; ++q) {
        float2 t = *reinterpret_cast<float2*>(&X[lane * 34 + 2 * q]);
        PY[q] = pk(t.x, t.y);
    }

    stages5(PX, PY, cs2);          // bits 5..9

#pragma unroll
    for (int q = 0; q < 16; ++q) {
        float xl, xh, yl, yh;
        upk(PX[q], xl, xh); upk(PY[q], yl, yh);
        out[base + (2 * q) * 32 + lane]     = make_float2(xl, yl);
        out[base + (2 * q + 1) * 32 + lane] = make_float2(xh, yh);
    }
}

// ---------------------------------------------------------------------------
// Pass B: global bits 10..19 for an 8-batch group, in place.
// Reads are last-use of the L2-resident intermediate (__ldcs = evict-first);
// writes are final dead data (__stcs = evict early, frees L2 for next group).
// ---------------------------------------------------------------------------
__global__ void __launch_bounds__(256)
rx_b(const float* __restrict__ thetas, float2* __restrict__ st, int batch_base)
{
    __shared__ float sm[32 * 264];
    const int t   = threadIdx.x;
    const int low = t & 7;
    const int g5  = t >> 3;
    const int blk   = blockIdx.x;              // 1024 blocks per group
    const int b     = batch_base + (blk >> 7);
    const int chunk = blk & 127;
    const long base = ((long)b << 20) + ((long)chunk << 3) + low;

    float2 cs1[5], cs2[5];
    load_cs(thetas, b, 10, cs1);
    load_cs(thetas, b, 15, cs2);

    u64 PX[16], PY[16];
    const long a0 = base + ((long)g5 << 15);
#pragma unroll
    for (int q = 0; q < 16; ++q) {
        float2 v0 = __ldcs(&st[a0 + ((long)(2 * q) << 10)]);
        float2 v1 = __ldcs(&st[a0 + ((long)(2 * q + 1) << 10)]);
        PX[q] = pk(v0.x, v1.x);
        PY[q] = pk(v0.y, v1.y);
    }

    stages5(PX, PY, cs1);           // bits 10..14

#pragma unroll
    for (int q = 0; q < 16; ++q) {
        float l, h; upk(PX[q], l, h);
        sm[g5 * 264 + (2 * q) * 8 + low]     = l;
        sm[g5 * 264 + (2 * q + 1) * 8 + low] = h;
    }
    __syncthreads();
#pragma unroll
    for (int q = 0; q < 16; ++q) {
        float l = sm[(2 * q) * 264 + g5 * 8 + low];
        float h = sm[(2 * q + 1) * 264 + g5 * 8 + low];
        PX[q] = pk(l, h);
    }
    __syncthreads();
#pragma unroll
    for (int q = 0; q < 16; ++q) {
        float l, h; upk(PY[q], l, h);
        sm[g5 * 264 + (2 * q) * 8 + low]     = l;
        sm[g5 * 264 + (2 * q + 1) * 8 + low] = h;
    }
    __syncthreads();
#pragma unroll
    for (int q = 0; q < 16; ++q) {
        float l = sm[(2 * q) * 264 + g5 * 8 + low];
        float h = sm[(2 * q + 1) * 264 + g5 * 8 + low];
        PY[q] = pk(l, h);
    }

    stages5(PX, PY, cs2);           // bits 15..19

    const long a1 = base + ((long)g5 << 10);
#pragma unroll
    for (int q = 0; q < 16; ++q) {
        float xl, xh, yl, yh;
        upk(PX[q], xl, xh); upk(PY[q], yl, yh);
        __stcs(&st[a1 + ((long)(2 * q) << 15)],     make_float2(xl, yl));
        __stcs(&st[a1 + ((long)(2 * q + 1) << 15)], make_float2(xh, yh));
    }
}

// ---------------------------------------------------------------------------
extern "C" void kernel_launch(void* const* d_in, const int* in_sizes, int n_in,
                              void* d_out, int out_size)
{
    const float* phi    = (const float*)d_in[0];   // [16, 2^20] float32
    const float* thetas = (const float*)d_in[1];   // [16, 20]   float32
    float2* out = (float2*)d_out;                  // [16, 2^20] (re, im)

    // Two 8-batch groups: each group's 64MB intermediate stays L2-resident
    // between its A and B passes, eliminating the intermediate DRAM round-trip.
    for (int g = 0; g < 2; ++g) {
        rx_a<<<1024, 256>>>(phi, thetas, out, g * 8);
        rx_b<<<1024, 256>>>(thetas, out, g * 8);
    }
}

// round 4
// speedup vs baseline: 2.0292x; 1.0471x over previous
#include <cuda_runtime.h>
#include <cuda_fp16.h>

#define NQ 20
typedef unsigned long long u64;
typedef unsigned int u32;

// 32MB scratch: fp16x2 intermediate for one 8-batch group (guaranteed L2-resident)
__device__ u32 g_scratch[8u << 20];

// ---------------- f32x2 helpers (packed 2xfp32 ops, sm_103a) ----------------
__device__ __forceinline__ u64 pk(float lo, float hi) {
    u64 r; asm("mov.b64 %0,{%1,%2};" : "=l"(r) : "f"(lo), "f"(hi)); return r;
}
__device__ __forceinline__ void upk(u64 p, float& lo, float& hi) {
    asm("mov.b64 {%0,%1},%2;" : "=f"(lo), "=f"(hi) : "l"(p));
}
__device__ __forceinline__ u64 f2mul(u64 a, u64 b) {
    u64 r; asm("mul.rn.f32x2 %0,%1,%2;" : "=l"(r) : "l"(a), "l"(b)); return r;
}
__device__ __forceinline__ u64 f2fma(u64 a, u64 b, u64 c) {
    u64 r; asm("fma.rn.f32x2 %0,%1,%2,%3;" : "=l"(r) : "l"(a), "l"(b), "l"(c)); return r;
}

// RX butterfly on pair (a,b), c=cos(th/2), s=sin(th/2):
//   na.x = c*ax + s*by ; na.y = c*ay - s*bx
//   nb.x = c*bx + s*ay ; nb.y = c*by - s*ax
__device__ __forceinline__ void stages5(u64 PX[16], u64 PY[16], const float2 cs[5])
{
    // stage 0: element mask 1 (intra-pack, packed swap)
    {
        u64 c2  = pk(cs[0].x,  cs[0].x);
        u64 s2  = pk(cs[0].y,  cs[0].y);
        u64 sn2 = pk(-cs[0].y, -cs[0].y);
#pragma unroll
        for (int q = 0; q < 16; ++q) {
            float xl, xh, yl, yh;
            upk(PX[q], xl, xh); upk(PY[q], yl, yh);
            u64 swx = pk(xh, xl), swy = pk(yh, yl);
            PX[q] = f2fma(c2, PX[q], f2mul(s2,  swy));
            PY[q] = f2fma(c2, PY[q], f2mul(sn2, swx));
        }
    }
    // stages 1..4: element mask 2^j -> pack mask 2^(j-1)
#pragma unroll
    for (int j = 1; j < 5; ++j) {
        u64 c2  = pk(cs[j].x,  cs[j].x);
        u64 s2  = pk(cs[j].y,  cs[j].y);
        u64 sn2 = pk(-cs[j].y, -cs[j].y);
        const int pm = 1 << (j - 1);
#pragma unroll
        for (int q = 0; q < 16; ++q) {
            if (!(q & pm)) {
                const int q2 = q | pm;
                u64 ax = PX[q], ay = PY[q], bx = PX[q2], by = PY[q2];
                PX[q]  = f2fma(c2, ax, f2mul(s2,  by));
                PY[q]  = f2fma(c2, ay, f2mul(sn2, bx));
                PX[q2] = f2fma(c2, bx, f2mul(s2,  ay));
                PY[q2] = f2fma(c2, by, f2mul(sn2, ax));
            }
        }
    }
}

// qubit i = most-significant bit => global bit g maps to theta index (19-g)
__device__ __forceinline__ void load_cs(const float* __restrict__ thetas, int b,
                                        int gbit_base, float2 cs[5])
{
#pragma unroll
    for (int j = 0; j < 5; ++j) {
        float th = thetas[b * NQ + (NQ - 1 - (gbit_base + j))];
        float s, c;
        __sincosf(0.5f * th, &s, &c);
        cs[j] = make_float2(c, s);
    }
}

// ---------------------------------------------------------------------------
// Pass A: global bits 0..9 for an 8-batch group. Warp owns 1024 contiguous
// elements. phi streamed in (__ldcs); fp16x2 intermediate to L2-resident scratch.
// ---------------------------------------------------------------------------
__global__ void __launch_bounds__(256)
rx_a(const float* __restrict__ phi, const float* __restrict__ thetas,
     int batch_base)
{
    __shared__ float sm[8][34 * 32];
    const int w    = threadIdx.x >> 5;
    const int lane = threadIdx.x & 31;
    const long gw  = (long)blockIdx.x * 8 + w;        // 8192 warps per group
    const int  bg  = (int)(gw >> 10);                 // batch within group
    const int  b   = batch_base + bg;
    const long ibase = ((long)bg << 20) + (long)(gw & 1023) * 1024;  // scratch idx
    const long pbase = ((long)b  << 20) + (long)(gw & 1023) * 1024;  // phi idx

    float2 cs1[5], cs2[5];
    load_cs(thetas, b, 0, cs1);
    load_cs(thetas, b, 5, cs2);

    u64 PX[16], PY[16];
    const float4* p4 = reinterpret_cast<const float4*>(phi + pbase + lane * 32);
#pragma unroll
    for (int k = 0; k < 8; ++k) {
        float4 t = __ldcs(p4 + k);          // streaming read-once
        PX[2 * k]     = pk(t.x, t.y);
        PX[2 * k + 1] = pk(t.z, t.w);
        PY[2 * k]     = 0ull;
        PY[2 * k + 1] = 0ull;
    }

    stages5(PX, PY, cs1);          // bits 0..4

    float* X = sm[w];
#pragma unroll
    for (int q = 0; q < 16; ++q) {
        float l, h; upk(PX[q], l, h);
        X[(2 * q) * 34 + lane]     = l;
        X[(2 * q + 1) * 34 + lane] = h;
    }
    __syncwarp();
#pragma unroll
    for (int q = 0; q < 16; ++q) {
        float2 t = *reinterpret_cast<float2*>(&X[lane * 34 + 2 * q]);
        PX[q] = pk(t.x, t.y);
    }
    __syncwarp();
#pragma unroll
    for (int q = 0; q < 16; ++q) {
        float l, h; upk(PY[q], l, h);
        X[(2 * q) * 34 + lane]     = l;
        X[(2 * q + 1) * 34 + lane] = h;
    }
    __syncwarp();
#pragma unroll
    for (int q = 0; q < 16; ++q) {
        float2 t = *reinterpret_cast<float2*>(&X[lane * 34 + 2 * q]);
        PY[q] = pk(t.x, t.y);
    }

    stages5(PX, PY, cs2);          // bits 5..9

    // store fp16x2 (x,y) per element; 32 lanes x 4B = 128B lines, default policy
#pragma unroll
    for (int q = 0; q < 16; ++q) {
        float xl, xh, yl, yh;
        upk(PX[q], xl, xh); upk(PY[q], yl, yh);
        __half2 h0 = __floats2half2_rn(xl, yl);
        __half2 h1 = __floats2half2_rn(xh, yh);
        g_scratch[ibase + (2 * q) * 32 + lane]     = *reinterpret_cast<u32*>(&h0);
        g_scratch[ibase + (2 * q + 1) * 32 + lane] = *reinterpret_cast<u32*>(&h1);
    }
}

// ---------------------------------------------------------------------------
// Pass B: global bits 10..19 for an 8-batch group.
// Reads fp16x2 intermediate (all L2-hit), writes final fp32 out (__stcs).
// ---------------------------------------------------------------------------
__global__ void __launch_bounds__(256)
rx_b(const float* __restrict__ thetas, float2* __restrict__ out, int batch_base)
{
    __shared__ float sm[32 * 264];
    const int t   = threadIdx.x;
    const int low = t & 7;
    const int g5  = t >> 3;
    const int blk   = blockIdx.x;              // 1024 blocks per group
    const int bg    = blk >> 7;
    const int b     = batch_base + bg;
    const int chunk = blk & 127;
    const long ibase = ((long)bg << 20) + ((long)chunk << 3) + low;  // scratch
    const long obase = ((long)b  << 20) + ((long)chunk << 3) + low;  // out

    float2 cs1[5], cs2[5];
    load_cs(thetas, b, 10, cs1);
    load_cs(thetas, b, 15, cs2);

    u64 PX[16], PY[16];
    const long a0 = ibase + ((long)g5 << 15);
#pragma unroll
    for (int q = 0; q < 16; ++q) {
        u32 w0 = g_scratch[a0 + ((long)(2 * q) << 10)];
        u32 w1 = g_scratch[a0 + ((long)(2 * q + 1) << 10)];
        float2 v0 = __half22float2(*reinterpret_cast<__half2*>(&w0));
        float2 v1 = __half22float2(*reinterpret_cast<__half2*>(&w1));
        PX[q] = pk(v0.x, v1.x);
        PY[q] = pk(v0.y, v1.y);
    }

    stages5(PX, PY, cs1);           // bits 10..14

#pragma unroll
    for (int q = 0; q < 16; ++q) {
        float l, h; upk(PX[q], l, h);
        sm[g5 * 264 + (2 * q) * 8 + low]     = l;
        sm[g5 * 264 + (2 * q + 1) * 8 + low] = h;
    }
    __syncthreads();
#pragma unroll
    for (int q = 0; q < 16; ++q) {
        float l = sm[(2 * q) * 264 + g5 * 8 + low];
        float h = sm[(2 * q + 1) * 264 + g5 * 8 + low];
        PX[q] = pk(l, h);
    }
    __syncthreads();
#pragma unroll
    for (int q = 0; q < 16; ++q) {
        float l, h; upk(PY[q], l, h);
        sm[g5 * 264 + (2 * q) * 8 + low]     = l;
        sm[g5 * 264 + (2 * q + 1) * 8 + low] = h;
    }
    __syncthreads();
#pragma unroll
    for (int q = 0; q < 16; ++q) {
        float l = sm[(2 * q) * 264 + g5 * 8 + low];
        float h = sm[(2 * q + 1) * 264 + g5 * 8 + low];
        PY[q] = pk(l, h);
    }

    stages5(PX, PY, cs2);           // bits 15..19

    const long a1 = obase + ((long)g5 << 10);
#pragma unroll
    for (int q = 0; q < 16; ++q) {
        float xl, xh, yl, yh;
        upk(PX[q], xl, xh); upk(PY[q], yl, yh);
        __stcs(&out[a1 + ((long)(2 * q) << 15)],     make_float2(xl, yl));
        __stcs(&out[a1 + ((long)(2 * q + 1) << 15)], make_float2(xh, yh));
    }
}

// ---------------------------------------------------------------------------
extern "C" void kernel_launch(void* const* d_in, const int* in_sizes, int n_in,
                              void* d_out, int out_size)
{
    const float* phi    = (const float*)d_in[0];   // [16, 2^20] float32
    const float* thetas = (const float*)d_in[1];   // [16, 20]   float32
    float2* out = (float2*)d_out;                  // [16, 2^20] (re, im)

    // Two 8-batch groups; each group's 32MB fp16x2 intermediate lives in a
    // dedicated scratch that stays L2-resident between its A and B passes.
    for (int g = 0; g < 2; ++g) {
        rx_a<<<1024, 256>>>(phi, thetas, g * 8);
        rx_b<<<1024, 256>>>(thetas, out, g * 8);
    }
}

// round 6
// speedup vs baseline: 2.2072x; 1.0877x over previous
#include <cuda_runtime.h>
#include <cuda_fp16.h>

#define NQ 20
typedef unsigned long long u64;
typedef unsigned int u32;

// 32MB scratch: fp16x2 intermediate for one 8-batch group (L2-resident)
__device__ u32 g_scratch[8u << 20];

// ---------------- f32x2 helpers (packed 2xfp32 ops, sm_103a) ----------------
__device__ __forceinline__ u64 pk(float lo, float hi) {
    u64 r; asm("mov.b64 %0,{%1,%2};" : "=l"(r) : "f"(lo), "f"(hi)); return r;
}
__device__ __forceinline__ void upk(u64 p, float& lo, float& hi) {
    asm("mov.b64 {%0,%1},%2;" : "=f"(lo), "=f"(hi) : "l"(p));
}
__device__ __forceinline__ u64 f2mul(u64 a, u64 b) {
    u64 r; asm("mul.rn.f32x2 %0,%1,%2;" : "=l"(r) : "l"(a), "l"(b)); return r;
}
__device__ __forceinline__ u64 f2fma(u64 a, u64 b, u64 c) {
    u64 r; asm("fma.rn.f32x2 %0,%1,%2,%3;" : "=l"(r) : "l"(a), "l"(b), "l"(c)); return r;
}

// ---------------- fast-Givens RX stages ----------------
// Unscaled update with t = tan(th/2):
//   ax' = ax + t*by ; ay' = ay - t*bx ; bx' = bx + t*ay ; by' = by - t*ax
// True result = (prod of cos) * unscaled; scale applied once per phase.

// stage 0: element mask 1 (intra-pack), scalar fma on the halves (no swaps)
__device__ __forceinline__ void stage0_fg(u64 PX[16], u64 PY[16], float tt)
{
#pragma unroll
    for (int q = 0; q < 16; ++q) {
        float xl, xh, yl, yh;
        upk(PX[q], xl, xh); upk(PY[q], yl, yh);
        PX[q] = pk(fmaf(tt, yh, xl), fmaf(tt, yl, xh));
        PY[q] = pk(fmaf(-tt, xh, yl), fmaf(-tt, xl, yh));
    }
}

// stages 1..4: pack-level pairs, 4 f2fma per pair
__device__ __forceinline__ void stages_fg_tail(u64 PX[16], u64 PY[16], const float t[5])
{
#pragma unroll
    for (int j = 1; j < 5; ++j) {
        u64 t2  = pk(t[j],  t[j]);
        u64 tn2 = pk(-t[j], -t[j]);
        const int pm = 1 << (j - 1);
#pragma unroll
        for (int q = 0; q < 16; ++q) {
            if (!(q & pm)) {
                const int q2 = q | pm;
                u64 ax = PX[q], bx = PX[q2];
                PX[q]  = f2fma(t2,  PY[q2], ax);
                PX[q2] = f2fma(t2,  PY[q],  bx);
                PY[q]  = f2fma(tn2, bx, PY[q]);
                PY[q2] = f2fma(tn2, ax, PY[q2]);
            }
        }
    }
}

__device__ __forceinline__ void scale_all(u64 PX[16], u64 PY[16], float C)
{
    u64 C2 = pk(C, C);
#pragma unroll
    for (int q = 0; q < 16; ++q) {
        PX[q] = f2mul(C2, PX[q]);
        PY[q] = f2mul(C2, PY[q]);
    }
}

// qubit i = most-significant bit => global bit g maps to theta index (19-g)
// fills t[j] = tan(th/2), returns product of cos(th/2)
__device__ __forceinline__ float load_tc(const float* __restrict__ thetas, int b,
                                         int gbit_base, float t[5])
{
    float C = 1.0f;
#pragma unroll
    for (int j = 0; j < 5; ++j) {
        float th = thetas[b * NQ + (NQ - 1 - (gbit_base + j))];
        float s, c;
        __sincosf(0.5f * th, &s, &c);
        t[j] = __fdividef(s, c);
        C *= c;
    }
    return C;
}

// ---------------------------------------------------------------------------
// Pass A: global bits 0..9 for an 8-batch group. Warp owns 1024 contiguous
// elements. phi streamed in (__ldcs); fp16x2 intermediate to scratch.
// Input is real: first stage specialized (PY = -t * swap(PX)).
// ---------------------------------------------------------------------------
__global__ void __launch_bounds__(256)
rx_a(const float* __restrict__ phi, const float* __restrict__ thetas,
     int batch_base)
{
    __shared__ float sm[8][34 * 32];
    const int w    = threadIdx.x >> 5;
    const int lane = threadIdx.x & 31;
    const long gw  = (long)blockIdx.x * 8 + w;        // 8192 warps per group
    const int  bg  = (int)(gw >> 10);
    const int  b   = batch_base + bg;
    const long ibase = ((long)bg << 20) + (long)(gw & 1023) * 1024;
    const long pbase = ((long)b  << 20) + (long)(gw & 1023) * 1024;

    float t1[5], t2[5];
    float C1 = load_tc(thetas, b, 0, t1);
    float C2 = load_tc(thetas, b, 5, t2);
    const float Ct = C1 * C2;

    u64 PX[16], PY[16];
    const float4* p4 = reinterpret_cast<const float4*>(phi + pbase + lane * 32);
#pragma unroll
    for (int k = 0; k < 8; ++k) {
        float4 v = __ldcs(p4 + k);
        PX[2 * k]     = pk(v.x, v.y);
        PX[2 * k + 1] = pk(v.z, v.w);
    }

    // specialized stage 0 with imag = 0: PX unchanged, PY = -t * swap(PX)
    {
        const float tn = -t1[0];
#pragma unroll
        for (int q = 0; q < 16; ++q) {
            float xl, xh; upk(PX[q], xl, xh);
            PY[q] = pk(tn * xh, tn * xl);
        }
    }
    stages_fg_tail(PX, PY, t1);    // bits 1..4

    float* X = sm[w];
#pragma unroll
    for (int q = 0; q < 16; ++q) {
        float l, h; upk(PX[q], l, h);
        X[(2 * q) * 34 + lane]     = l;
        X[(2 * q + 1) * 34 + lane] = h;
    }
    __syncwarp();
#pragma unroll
    for (int q = 0; q < 16; ++q) {
        float2 v = *reinterpret_cast<float2*>(&X[lane * 34 + 2 * q]);
        PX[q] = pk(v.x, v.y);
    }
    __syncwarp();
#pragma unroll
    for (int q = 0; q < 16; ++q) {
        float l, h; upk(PY[q], l, h);
        X[(2 * q) * 34 + lane]     = l;
        X[(2 * q + 1) * 34 + lane] = h;
    }
    __syncwarp();
#pragma unroll
    for (int q = 0; q < 16; ++q) {
        float2 v = *reinterpret_cast<float2*>(&X[lane * 34 + 2 * q]);
        PY[q] = pk(v.x, v.y);
    }

    stage0_fg(PX, PY, t2[0]);      // bit 5
    stages_fg_tail(PX, PY, t2);    // bits 6..9

    scale_all(PX, PY, Ct);         // apply deferred cos product once

#pragma unroll
    for (int q = 0; q < 16; ++q) {
        float xl, xh, yl, yh;
        upk(PX[q], xl, xh); upk(PY[q], yl, yh);
        __half2 h0 = __floats2half2_rn(xl, yl);
        __half2 h1 = __floats2half2_rn(xh, yh);
        g_scratch[ibase + (2 * q) * 32 + lane]     = *reinterpret_cast<u32*>(&h0);
        g_scratch[ibase + (2 * q + 1) * 32 + lane] = *reinterpret_cast<u32*>(&h1);
    }
}

// ---------------------------------------------------------------------------
// Pass B: global bits 10..19 for an 8-batch group.
// Reads fp16x2 intermediate (L2-hit), writes final fp32 out (__stcs).
// ---------------------------------------------------------------------------
__global__ void __launch_bounds__(256)
rx_b(const float* __restrict__ thetas, float2* __restrict__ out, int batch_base)
{
    __shared__ float sm[32 * 264];
    const int t   = threadIdx.x;
    const int low = t & 7;
    const int g5  = t >> 3;
    const int blk   = blockIdx.x;              // 1024 blocks per group
    const int bg    = blk >> 7;
    const int b     = batch_base + bg;
    const int chunk = blk & 127;
    const long ibase = ((long)bg << 20) + ((long)chunk << 3) + low;
    const long obase = ((long)b  << 20) + ((long)chunk << 3) + low;

    float t1[5], t2[5];
    float C1 = load_tc(thetas, b, 10, t1);
    float C2 = load_tc(thetas, b, 15, t2);
    const float Ct = C1 * C2;

    u64 PX[16], PY[16];
    const long a0 = ibase + ((long)g5 << 15);
#pragma unroll
    for (int q = 0; q < 16; ++q) {
        u32 w0 = g_scratch[a0 + ((long)(2 * q) << 10)];
        u32 w1 = g_scratch[a0 + ((long)(2 * q + 1) << 10)];
        float2 v0 = __half22float2(*reinterpret_cast<__half2*>(&w0));
        float2 v1 = __half22float2(*reinterpret_cast<__half2*>(&w1));
        PX[q] = pk(v0.x, v1.x);
        PY[q] = pk(v0.y, v1.y);
    }

    stage0_fg(PX, PY, t1[0]);      // bit 10
    stages_fg_tail(PX, PY, t1);    // bits 11..14

#pragma unroll
    for (int q = 0; q < 16; ++q) {
        float l, h; upk(PX[q], l, h);
        sm[g5 * 264 + (2 * q) * 8 + low]     = l;
        sm[g5 * 264 + (2 * q + 1) * 8 + low] = h;
    }
    __syncthreads();
#pragma unroll
    for (int q = 0; q < 16; ++q) {
        float l = sm[(2 * q) * 264 + g5 * 8 + low];
        float h = sm[(2 * q + 1) * 264 + g5 * 8 + low];
        PX[q] = pk(l, h);
    }
    __syncthreads();
#pragma unroll
    for (int q = 0; q < 16; ++q) {
        float l, h; upk(PY[q], l, h);
        sm[g5 * 264 + (2 * q) * 8 + low]     = l;
        sm[g5 * 264 + (2 * q + 1) * 8 + low] = h;
    }
    __syncthreads();
#pragma unroll
    for (int q = 0; q < 16; ++q) {
        float l = sm[(2 * q) * 264 + g5 * 8 + low];
        float h = sm[(2 * q + 1) * 264 + g5 * 8 + low];
        PY[q] = pk(l, h);
    }

    stage0_fg(PX, PY, t2[0]);      // bit 15
    stages_fg_tail(PX, PY, t2);    // bits 16..19

    scale_all(PX, PY, Ct);         // deferred cos product

    const long a1 = obase + ((long)g5 << 10);
#pragma unroll
    for (int q = 0; q < 16; ++q) {
        float xl, xh, yl, yh;
        upk(PX[q], xl, xh); upk(PY[q], yl, yh);
        __stcs(&out[a1 + ((long)(2 * q) << 15)],     make_float2(xl, yl));
        __stcs(&out[a1 + ((long)(2 * q + 1) << 15)], make_float2(xh, yh));
    }
}

// ---------------------------------------------------------------------------
extern "C" void kernel_launch(void* const* d_in, const int* in_sizes, int n_in,
                              void* d_out, int out_size)
{
    const float* phi    = (const float*)d_in[0];   // [16, 2^20] float32
    const float* thetas = (const float*)d_in[1];   // [16, 20]   float32
    float2* out = (float2*)d_out;                  // [16, 2^20] (re, im)

    for (int g = 0; g < 2; ++g) {
        rx_a<<<1024, 256>>>(phi, thetas, g * 8);
        rx_b<<<1024, 256>>>(thetas, out, g * 8);
    }
}

// round 7
// speedup vs baseline: 2.3106x; 1.0468x over previous
#include <cuda_runtime.h>
#include <cuda_fp16.h>

#define NQ 20
typedef unsigned long long u64;
typedef unsigned int u32;

// 64MB scratch: fp16x2 intermediate for all 16 batches (fits 126MB L2)
__device__ u32 g_scratch[16u << 20];

// ---------------- f32x2 helpers (packed 2xfp32 ops, sm_103a) ----------------
__device__ __forceinline__ u64 pk(float lo, float hi) {
    u64 r; asm("mov.b64 %0,{%1,%2};" : "=l"(r) : "f"(lo), "f"(hi)); return r;
}
__device__ __forceinline__ void upk(u64 p, float& lo, float& hi) {
    asm("mov.b64 {%0,%1},%2;" : "=f"(lo), "=f"(hi) : "l"(p));
}
__device__ __forceinline__ u64 f2mul(u64 a, u64 b) {
    u64 r; asm("mul.rn.f32x2 %0,%1,%2;" : "=l"(r) : "l"(a), "l"(b)); return r;
}
__device__ __forceinline__ u64 f2fma(u64 a, u64 b, u64 c) {
    u64 r; asm("fma.rn.f32x2 %0,%1,%2,%3;" : "=l"(r) : "l"(a), "l"(b), "l"(c)); return r;
}

// ---------------- fast-Givens RX stages ----------------
// Unscaled update with t = tan(th/2):
//   ax' = ax + t*by ; ay' = ay - t*bx ; bx' = bx + t*ay ; by' = by - t*ax
// True result = (prod of cos) * unscaled; scale applied once per phase.

// stage 0: element mask 1 (intra-pack), scalar fma on the halves
__device__ __forceinline__ void stage0_fg(u64 PX[16], u64 PY[16], float tt)
{
#pragma unroll
    for (int q = 0; q < 16; ++q) {
        float xl, xh, yl, yh;
        upk(PX[q], xl, xh); upk(PY[q], yl, yh);
        PX[q] = pk(fmaf(tt, yh, xl), fmaf(tt, yl, xh));
        PY[q] = pk(fmaf(-tt, xh, yl), fmaf(-tt, xl, yh));
    }
}

// stages 1..4: pack-level pairs, 4 f2fma per pair
__device__ __forceinline__ void stages_fg_tail(u64 PX[16], u64 PY[16], const float t[5])
{
#pragma unroll
    for (int j = 1; j < 5; ++j) {
        u64 t2  = pk(t[j],  t[j]);
        u64 tn2 = pk(-t[j], -t[j]);
        const int pm = 1 << (j - 1);
#pragma unroll
        for (int q = 0; q < 16; ++q) {
            if (!(q & pm)) {
                const int q2 = q | pm;
                u64 ax = PX[q], bx = PX[q2];
                PX[q]  = f2fma(t2,  PY[q2], ax);
                PX[q2] = f2fma(t2,  PY[q],  bx);
                PY[q]  = f2fma(tn2, bx, PY[q]);
                PY[q2] = f2fma(tn2, ax, PY[q2]);
            }
        }
    }
}

__device__ __forceinline__ void scale_all(u64 PX[16], u64 PY[16], float C)
{
    u64 C2 = pk(C, C);
#pragma unroll
    for (int q = 0; q < 16; ++q) {
        PX[q] = f2mul(C2, PX[q]);
        PY[q] = f2mul(C2, PY[q]);
    }
}

// qubit i = most-significant bit => global bit g maps to theta index (19-g)
// fills t[j] = tan(th/2), returns product of cos(th/2)
__device__ __forceinline__ float load_tc(const float* __restrict__ thetas, int b,
                                         int gbit_base, float t[5])
{
    float C = 1.0f;
#pragma unroll
    for (int j = 0; j < 5; ++j) {
        float th = thetas[b * NQ + (NQ - 1 - (gbit_base + j))];
        float s, c;
        __sincosf(0.5f * th, &s, &c);
        t[j] = __fdividef(s, c);
        C *= c;
    }
    return C;
}

// ---------------------------------------------------------------------------
// Pass A: global bits 0..9, all 16 batches. Warp owns 1024 contiguous
// elements. phi streamed in (__ldcs); fp16x2 intermediate to scratch.
// ---------------------------------------------------------------------------
__global__ void __launch_bounds__(256)
rx_a(const float* __restrict__ phi, const float* __restrict__ thetas)
{
    __shared__ float sm[8][34 * 32];
    const int w    = threadIdx.x >> 5;
    const int lane = threadIdx.x & 31;
    const u32 gw   = blockIdx.x * 8 + w;       // 16384 warps
    const int b    = gw >> 10;
    const u32 base = gw << 10;

    float t1[5], t2[5];
    float C1 = load_tc(thetas, b, 0, t1);
    float C2 = load_tc(thetas, b, 5, t2);
    const float Ct = C1 * C2;

    u64 PX[16], PY[16];
    const float4* p4 = reinterpret_cast<const float4*>(phi + base + lane * 32);
#pragma unroll
    for (int k = 0; k < 8; ++k) {
        float4 v = __ldcs(p4 + k);
        PX[2 * k]     = pk(v.x, v.y);
        PX[2 * k + 1] = pk(v.z, v.w);
    }

    // specialized stage 0 with imag = 0: PX unchanged, PY = -t * swap(PX)
    {
        const float tn = -t1[0];
#pragma unroll
        for (int q = 0; q < 16; ++q) {
            float xl, xh; upk(PX[q], xl, xh);
            PY[q] = pk(tn * xh, tn * xl);
        }
    }
    stages_fg_tail(PX, PY, t1);    // bits 1..4

    float* X = sm[w];
#pragma unroll
    for (int q = 0; q < 16; ++q) {
        float l, h; upk(PX[q], l, h);
        X[(2 * q) * 34 + lane]     = l;
        X[(2 * q + 1) * 34 + lane] = h;
    }
    __syncwarp();
#pragma unroll
    for (int q = 0; q < 16; ++q) {
        float2 v = *reinterpret_cast<float2*>(&X[lane * 34 + 2 * q]);
        PX[q] = pk(v.x, v.y);
    }
    __syncwarp();
#pragma unroll
    for (int q = 0; q < 16; ++q) {
        float l, h; upk(PY[q], l, h);
        X[(2 * q) * 34 + lane]     = l;
        X[(2 * q + 1) * 34 + lane] = h;
    }
    __syncwarp();
#pragma unroll
    for (int q = 0; q < 16; ++q) {
        float2 v = *reinterpret_cast<float2*>(&X[lane * 34 + 2 * q]);
        PY[q] = pk(v.x, v.y);
    }

    stage0_fg(PX, PY, t2[0]);      // bit 5
    stages_fg_tail(PX, PY, t2);    // bits 6..9

    scale_all(PX, PY, Ct);

#pragma unroll
    for (int q = 0; q < 16; ++q) {
        float xl, xh, yl, yh;
        upk(PX[q], xl, xh); upk(PY[q], yl, yh);
        __half2 h0 = __floats2half2_rn(xl, yl);
        __half2 h1 = __floats2half2_rn(xh, yh);
        g_scratch[base + (2 * q) * 32 + lane]     = *reinterpret_cast<u32*>(&h0);
        g_scratch[base + (2 * q + 1) * 32 + lane] = *reinterpret_cast<u32*>(&h1);
    }
}

// ---------------------------------------------------------------------------
// Pass B: global bits 10..19, all 16 batches.
// Reads fp16x2 intermediate (L2-resident), writes final fp32 out (__stcs).
// Single-barrier transpose: X and Y pack-stored (STS64) into two smem
// regions, one __syncthreads, then conflict-free 32-bit gathers.
// Pack-store layout per array: u64 at [i5]*136 + [j5pair]*8 + [low]
//   -> float (i5, j5) at i5*272 + (j5>>1)*16 + low*2 + (j5&1)
// ---------------------------------------------------------------------------
__global__ void __launch_bounds__(256)
rx_b(const float* __restrict__ thetas, float2* __restrict__ out)
{
    __shared__ u64 smq[2 * 32 * 136];          // 69632 B
    const int t   = threadIdx.x;
    const int low = t & 7;
    const int g5  = t >> 3;
    const int blk   = blockIdx.x;              // 2048 blocks
    const int b     = blk >> 7;
    const int chunk = blk & 127;
    const u32 base  = ((u32)b << 20) + ((u32)chunk << 3) + (u32)low;

    float t1[5];
    float C1 = load_tc(thetas, b, 10, t1);

    // loads: two batches of 16 issued before their converts (MLP)
    u64 PX[16], PY[16];
    const u32 a0 = base + ((u32)g5 << 15);
#pragma unroll
    for (int h = 0; h < 2; ++h) {
        u32 wv[16];
#pragma unroll
        for (int k = 0; k < 16; ++k)
            wv[k] = __ldcs(&g_scratch[a0 + (u32)(h * 16 + k) * 1024u]);
#pragma unroll
        for (int k = 0; k < 8; ++k) {
            const int q = h * 8 + k;
            float2 v0 = __half22float2(*reinterpret_cast<__half2*>(&wv[2 * k]));
            float2 v1 = __half22float2(*reinterpret_cast<__half2*>(&wv[2 * k + 1]));
            PX[q] = pk(v0.x, v1.x);
            PY[q] = pk(v0.y, v1.y);
        }
    }

    stage0_fg(PX, PY, t1[0]);      // bit 10
    stages_fg_tail(PX, PY, t1);    // bits 11..14

    // pack-store X and Y (STS64), one barrier
#pragma unroll
    for (int q = 0; q < 16; ++q) {
        smq[g5 * 136 + q * 8 + low]              = PX[q];
        smq[32 * 136 + g5 * 136 + q * 8 + low]   = PY[q];
    }
    __syncthreads();

    const float* smf = reinterpret_cast<const float*>(smq);
    const int ro = ((g5 >> 1) << 4) + (low << 1) + (g5 & 1);
#pragma unroll
    for (int q = 0; q < 16; ++q) {
        PX[q] = pk(smf[(2 * q) * 272 + ro],        smf[(2 * q + 1) * 272 + ro]);
        PY[q] = pk(smf[8704 + (2 * q) * 272 + ro], smf[8704 + (2 * q + 1) * 272 + ro]);
    }

    float t2[5];
    float C2 = load_tc(thetas, b, 15, t2);

    stage0_fg(PX, PY, t2[0]);      // bit 15
    stages_fg_tail(PX, PY, t2);    // bits 16..19

    scale_all(PX, PY, C1 * C2);

    const u32 a1 = base + ((u32)g5 << 10);
#pragma unroll
    for (int q = 0; q < 16; ++q) {
        float xl, xh, yl, yh;
        upk(PX[q], xl, xh); upk(PY[q], yl, yh);
        __stcs(&out[a1 + ((u32)(2 * q) << 15)],     make_float2(xl, yl));
        __stcs(&out[a1 + ((u32)(2 * q + 1) << 15)], make_float2(xh, yh));
    }
}

// ---------------------------------------------------------------------------
extern "C" void kernel_launch(void* const* d_in, const int* in_sizes, int n_in,
                              void* d_out, int out_size)
{
    const float* phi    = (const float*)d_in[0];   // [16, 2^20] float32
    const float* thetas = (const float*)d_in[1];   // [16, 20]   float32
    float2* out = (float2*)d_out;                  // [16, 2^20] (re, im)

    rx_a<<<2048, 256>>>(phi, thetas);
    rx_b<<<2048, 256>>>(thetas, out);
}